// round 17
// baseline (speedup 1.0000x reference)
#include <cuda_runtime.h>
#include <cuda_bf16.h>
#include <stdint.h>
#include <math.h>

#define NNODES 50000
#define INCH   128
#define E_REAL 400000
#define E_TOT  450000

typedef unsigned int u32;

// ---------------- scratch (device globals) ----------------------------------
__device__ __align__(16) float g_H1[(size_t)NNODES * 256];
__device__ __align__(16) float g_H2[(size_t)NNODES * 128];
__device__ __align__(16) __nv_bfloat16 g_xhi[(size_t)NNODES * 128];
__device__ __align__(16) __nv_bfloat16 g_xlo[(size_t)NNODES * 128];
__device__ __align__(16) __nv_bfloat16 g_O1hi[(size_t)NNODES * 256];
__device__ __align__(16) __nv_bfloat16 g_O1lo[(size_t)NNODES * 256];
__device__ __align__(16) __nv_bfloat16 g_B1thi[256 * 128];
__device__ __align__(16) __nv_bfloat16 g_B1tlo[256 * 128];
__device__ __align__(16) __nv_bfloat16 g_B2thi[128 * 256];
__device__ __align__(16) __nv_bfloat16 g_B2tlo[128 * 256];
__device__ __align__(16) float g_WA1[128 * 4];
__device__ float g_as1[NNODES * 2];
__device__ float g_ad1[NNODES * 2];
__device__ float g_as2[NNODES * 2];
__device__ float g_ad2[NNODES * 2];
__device__ int   g_deg[NNODES + 1];
__device__ int   g_off[NNODES + 1];
__device__ int   g_cur[NNODES];
__device__ int   g_blockSums[256];
__device__ int   g_srcList[E_TOT];
__device__ float g_attS2[128];
__device__ float g_attD2[128];

#define SCAN_BLOCKS ((NNODES + 255) / 256)   // 196

// ---------------- small utility kernels -------------------------------------
__global__ void zero_int_kernel(int* p, int n)
{
    int i = blockIdx.x * blockDim.x + threadIdx.x;
    if (i < n) { p[i] = 0; }
}

__global__ void hist_kernel(const int* __restrict__ ei, int* __restrict__ deg)
{
    int i = blockIdx.x * blockDim.x + threadIdx.x;
    if (i >= E_TOT) { return; }
    int dst = (i < E_REAL) ? ei[E_REAL + i] : (i - E_REAL);
    atomicAdd(&deg[dst], 1);
}

// phase A: per-block exclusive scan of 256 degrees; block sum out
__global__ void scanA_kernel(const int* __restrict__ deg,
                             int* __restrict__ off,
                             int* __restrict__ blockSums)
{
    __shared__ int ws[8];
    int b = blockIdx.x;
    int t = threadIdx.x;
    int lane = t & 31;
    int wid = t >> 5;
    int idx = b * 256 + t;
    int v = (idx < NNODES) ? deg[idx] : 0;
    int x = v;
    for (int o = 1; o < 32; o <<= 1) {
        int y = __shfl_up_sync(0xffffffffu, x, o);
        if (lane >= o) { x += y; }
    }
    if (lane == 31) { ws[wid] = x; }
    __syncthreads();
    if (wid == 0 && lane < 8) {
        int w = ws[lane];
        for (int o = 1; o < 8; o <<= 1) {
            int y = __shfl_up_sync(0xffu, w, o);
            if (lane >= o) { w += y; }
        }
        ws[lane] = w;
    }
    __syncthreads();
    int incl = x + ((wid > 0) ? ws[wid - 1] : 0);
    if (idx < NNODES) { off[idx] = incl - v; }
    if (t == 255) { blockSums[b] = incl; }
}

// phase B: single block scans the block sums into exclusive offsets
__global__ void scanB_kernel(int* __restrict__ blockSums)
{
    __shared__ int ws[8];
    int t = threadIdx.x;
    int lane = t & 31;
    int wid = t >> 5;
    int v = (t < SCAN_BLOCKS) ? blockSums[t] : 0;
    int x = v;
    for (int o = 1; o < 32; o <<= 1) {
        int y = __shfl_up_sync(0xffffffffu, x, o);
        if (lane >= o) { x += y; }
    }
    if (lane == 31) { ws[wid] = x; }
    __syncthreads();
    if (wid == 0 && lane < 8) {
        int w = ws[lane];
        for (int o = 1; o < 8; o <<= 1) {
            int y = __shfl_up_sync(0xffu, w, o);
            if (lane >= o) { w += y; }
        }
        ws[lane] = w;
    }
    __syncthreads();
    int incl = x + ((wid > 0) ? ws[wid - 1] : 0);
    if (t < SCAN_BLOCKS) { blockSums[t] = incl - v; }
}

// phase C: add block offsets; init cur
__global__ void scanC_kernel(int* __restrict__ off,
                             const int* __restrict__ blockSums,
                             int* __restrict__ cur)
{
    int i = blockIdx.x * 256 + threadIdx.x;
    if (i < NNODES) {
        int val = off[i] + blockSums[i >> 8];
        off[i] = val;
        cur[i] = val;
    }
    if (i == 0) { off[NNODES] = E_TOT; }
}

__global__ void scatter_kernel(const int* __restrict__ ei, int* __restrict__ cur,
                               int* __restrict__ srcList)
{
    int i = blockIdx.x * blockDim.x + threadIdx.x;
    if (i >= E_TOT) { return; }
    int src;
    int dst;
    if (i < E_REAL) { src = ei[i]; dst = ei[E_REAL + i]; }
    else            { src = i - E_REAL; dst = src; }
    int p = atomicAdd(&cur[dst], 1);
    srcList[p] = src;
}

__global__ void packW1_kernel(const float* __restrict__ W1,
                              __nv_bfloat16* __restrict__ hi,
                              __nv_bfloat16* __restrict__ lo)
{
    int i = blockIdx.x * blockDim.x + threadIdx.x;
    if (i >= 256 * 128) { return; }
    int nn = i >> 7;
    int kk = i & 127;
    float v = W1[kk * 256 + nn];
    __nv_bfloat16 h = __float2bfloat16(v);
    hi[i] = h;
    lo[i] = __float2bfloat16(v - __bfloat162float(h));
}

// blocks 0..127: pack [Wmu|Wls]; blocks 128-129: fold WA1; block 130: att2 pack
__global__ void packW2_kernel(const float* __restrict__ Wmu,
                              const float* __restrict__ Wls,
                              __nv_bfloat16* __restrict__ hi,
                              __nv_bfloat16* __restrict__ lo,
                              const float* __restrict__ W1,
                              const float* __restrict__ attS1,
                              const float* __restrict__ attD1,
                              const float* __restrict__ smu,
                              const float* __restrict__ sls,
                              const float* __restrict__ dmu,
                              const float* __restrict__ dls,
                              float* __restrict__ WA,
                              float* __restrict__ S,
                              float* __restrict__ D)
{
    int b = blockIdx.x;
    int t = threadIdx.x;
    if (b < 128) {
        int i = b * 256 + t;
        int nn = i >> 8;
        int kk = i & 255;
        float v = (nn < 64) ? Wmu[kk * 64 + nn] : Wls[kk * 64 + (nn - 64)];
        __nv_bfloat16 h = __float2bfloat16(v);
        hi[i] = h;
        lo[i] = __float2bfloat16(v - __bfloat162float(h));
    } else if (b < 130) {
        int it = (b - 128) * 256 + t;   // 0..511
        int k = it >> 2;
        int j = it & 3;
        int h = j & 1;
        const float* av = (j < 2) ? attS1 : attD1;
        float s = 0.0f;
        for (int c = 0; c < 128; c++) {
            s += W1[k * 256 + h * 128 + c] * av[h * 128 + c];
        }
        WA[k * 4 + j] = s;
    } else {
        if (t < 64) {
            S[t] = smu[t];
            S[64 + t] = sls[t];
            D[t] = dmu[t];
            D[64 + t] = dls[t];
        }
    }
}

// split x into bf16 hi/lo AND compute layer-1 attention dots (WA ready: earlier launch)
__global__ void split_dots_kernel(const float* __restrict__ x,
                                  const float* __restrict__ WA,
                                  __nv_bfloat16* __restrict__ xhi,
                                  __nv_bfloat16* __restrict__ xlo,
                                  float* __restrict__ as1,
                                  float* __restrict__ ad1)
{
    __shared__ float sdot[2][4];
    int b = blockIdx.x;
    int t = threadIdx.x;
    int ln = t >> 7;              // 0..1 local node
    int col = t & 127;
    int node = b * 2 + ln;
    if (t < 8) { sdot[t >> 2][t & 3] = 0.0f; }
    __syncthreads();
    if (node < NNODES) {
        float v = x[(size_t)node * 128 + col];
        __nv_bfloat16 h = __float2bfloat16(v);
        xhi[(size_t)node * 128 + col] = h;
        xlo[(size_t)node * 128 + col] = __float2bfloat16(v - __bfloat162float(h));
        const float* wp = WA + col * 4;
        float p0 = v * wp[0];
        float p1 = v * wp[1];
        float p2 = v * wp[2];
        float p3 = v * wp[3];
        for (int o = 16; o > 0; o >>= 1) {
            p0 += __shfl_xor_sync(0xffffffffu, p0, o);
            p1 += __shfl_xor_sync(0xffffffffu, p1, o);
            p2 += __shfl_xor_sync(0xffffffffu, p2, o);
            p3 += __shfl_xor_sync(0xffffffffu, p3, o);
        }
        if ((t & 31) == 0) {
            atomicAdd(&sdot[ln][0], p0);
            atomicAdd(&sdot[ln][1], p1);
            atomicAdd(&sdot[ln][2], p2);
            atomicAdd(&sdot[ln][3], p3);
        }
    }
    __syncthreads();
    if (t < 8) {
        int nn = b * 2 + (t >> 2);
        if (nn < NNODES) {
            int j = t & 3;
            float val = sdot[t >> 2][j];
            if (j < 2) { as1[2 * nn + j] = val; }
            else       { ad1[2 * nn + (j - 2)] = val; }
        }
    }
}

// ---------------- mma.sync / cp.async helpers --------------------------------
__device__ __forceinline__ u32 smem_u32(const void* p)
{
    u32 a;
    asm("{ .reg .u64 t; cvta.to.shared.u64 t, %1; cvt.u32.u64 %0, t; }"
        : "=r"(a) : "l"(p));
    return a;
}

__device__ __forceinline__ void ldsm4(u32* r, u32 addr)
{
    asm volatile("ldmatrix.sync.aligned.m8n8.x4.shared.b16 {%0,%1,%2,%3}, [%4];"
        : "=r"(r[0]), "=r"(r[1]), "=r"(r[2]), "=r"(r[3]) : "r"(addr));
}

__device__ __forceinline__ void mma16816(float* c, const u32* a, const u32* b)
{
    asm volatile("mma.sync.aligned.m16n8k16.row.col.f32.bf16.bf16.f32 "
        "{%0,%1,%2,%3}, {%4,%5,%6,%7}, {%8,%9}, {%0,%1,%2,%3};"
        : "+f"(c[0]), "+f"(c[1]), "+f"(c[2]), "+f"(c[3])
        : "r"(a[0]), "r"(a[1]), "r"(a[2]), "r"(a[3]), "r"(b[0]), "r"(b[1]));
}

__device__ __forceinline__ void cpa16(u32 dst, const void* src, int szbytes)
{
    asm volatile("cp.async.cg.shared.global [%0], [%1], 16, %2;"
        :: "r"(dst), "l"(src), "r"(szbytes));
}

__device__ __forceinline__ void cpa_commit()
{
    asm volatile("cp.async.commit_group;");
}

template <int NN>
__device__ __forceinline__ void cpa_wait()
{
    asm volatile("cp.async.wait_group %0;" :: "n"(NN));
}

// smem stage (bytes): A_hi[128][40] | A_lo | B_hi[128][40] | B_lo  (pitch 80B)
#define STG_AHI 0
#define STG_ALO 10240
#define STG_BHI 20480
#define STG_BLO 30720
#define STG_BYTES 40960
#define GEMM_SMEM (2 * STG_BYTES)

// ---------------- pipelined bf16x3 mma.sync GEMM (128x128 CTA tile) ----------
template <int KCH, bool DOTS>
__global__ __launch_bounds__(256, 2)
void gemm_mma_kernel(const __nv_bfloat16* __restrict__ Ahi,
                     const __nv_bfloat16* __restrict__ Alo,
                     const __nv_bfloat16* __restrict__ Bthi,
                     const __nv_bfloat16* __restrict__ Btlo,
                     float* __restrict__ C, int M, int ldn,
                     const float* __restrict__ Sv,
                     const float* __restrict__ Dv,
                     float* __restrict__ dotS,
                     float* __restrict__ dotD)
{
    extern __shared__ char smem[];
    const int KTOT = KCH * 32;
    u32 sb = smem_u32(smem);
    int tid = threadIdx.x;
    int warp = tid >> 5;
    int lane = tid & 31;
    int wm = warp >> 1;                 // 0..3 (32-row slabs)
    int wn = warp & 1;                  // 0..1 (64-col slabs)
    int m0 = blockIdx.y * 128;
    int n0 = blockIdx.x * 128;

    float acc[2][8][4];
    for (int a = 0; a < 2; a++) {
        for (int b = 0; b < 8; b++) {
            for (int c = 0; c < 4; c++) { acc[a][b][c] = 0.0f; }
        }
    }

    auto issue = [&](int kc, int buf) {
        u32 base = sb + buf * STG_BYTES;
        for (int i = 0; i < 2; i++) {
            int c = tid + 256 * i;
            int r = c >> 2;              // 0..127
            int kk = (c & 3) * 8;        // 0,8,16,24
            u32 off = (u32)(r * 80 + kk * 2);
            int grow = m0 + r;
            int gcol = kc * 32 + kk;
            size_t asrc = (size_t)((grow < M) ? grow : 0) * KTOT + gcol;
            int sz = (grow < M) ? 16 : 0;
            cpa16(base + STG_AHI + off, Ahi + asrc, sz);
            cpa16(base + STG_ALO + off, Alo + asrc, sz);
            size_t bsrc = (size_t)(n0 + r) * KTOT + gcol;
            cpa16(base + STG_BHI + off, Bthi + bsrc, 16);
            cpa16(base + STG_BLO + off, Btlo + bsrc, 16);
        }
    };

    auto compute = [&](int buf) {
        u32 base = sb + buf * STG_BYTES;
        for (int ks = 0; ks < 2; ks++) {
            int colOff = ks * 16 + ((lane >> 4) << 3);
            int rsel = lane & 15;
            u32 Ah[2][4];
            u32 Al[2][4];
            for (int mf = 0; mf < 2; mf++) {
                int row = wm * 32 + mf * 16 + rsel;
                ldsm4(Ah[mf], base + STG_AHI + row * 80 + colOff * 2);
                ldsm4(Al[mf], base + STG_ALO + row * 80 + colOff * 2);
            }
            for (int ph = 0; ph < 2; ph++) {
                u32 Bh[4][2];
                u32 Bl[4][2];
                for (int p = 0; p < 2; p++) {
                    int row = wn * 64 + (ph * 2 + p) * 16 + rsel;
                    u32 t[4];
                    ldsm4(t, base + STG_BHI + row * 80 + colOff * 2);
                    Bh[2 * p][0] = t[0];
                    Bh[2 * p][1] = t[2];
                    Bh[2 * p + 1][0] = t[1];
                    Bh[2 * p + 1][1] = t[3];
                    ldsm4(t, base + STG_BLO + row * 80 + colOff * 2);
                    Bl[2 * p][0] = t[0];
                    Bl[2 * p][1] = t[2];
                    Bl[2 * p + 1][0] = t[1];
                    Bl[2 * p + 1][1] = t[3];
                }
                for (int mf = 0; mf < 2; mf++) {
                    for (int nf = 0; nf < 4; nf++) {
                        float* a = acc[mf][ph * 4 + nf];
                        mma16816(a, Ah[mf], Bh[nf]);
                        mma16816(a, Ah[mf], Bl[nf]);
                        mma16816(a, Al[mf], Bh[nf]);
                    }
                }
            }
        }
    };

    issue(0, 0);
    cpa_commit();
    for (int kc = 0; kc < KCH; kc++) {
        if (kc + 1 < KCH) {
            issue(kc + 1, (kc + 1) & 1);
            cpa_commit();
            cpa_wait<1>();
        } else {
            cpa_wait<0>();
        }
        __syncthreads();
        compute(kc & 1);
        __syncthreads();
    }

    for (int mf = 0; mf < 2; mf++) {
        int r0 = m0 + wm * 32 + mf * 16 + (lane >> 2);
        for (int nf = 0; nf < 8; nf++) {
            int cb = n0 + wn * 64 + nf * 8 + (lane & 3) * 2;
            if (r0 < M) {
                float2 v;
                v.x = acc[mf][nf][0];
                v.y = acc[mf][nf][1];
                *(float2*)&C[(size_t)r0 * ldn + cb] = v;
            }
            if (r0 + 8 < M) {
                float2 v;
                v.x = acc[mf][nf][2];
                v.y = acc[mf][nf][3];
                *(float2*)&C[(size_t)(r0 + 8) * ldn + cb] = v;
            }
        }
    }

    if (DOTS) {
        int head = (n0 + wn * 64) >> 6;
        for (int mf = 0; mf < 2; mf++) {
            float sA0 = 0.0f;
            float sD0 = 0.0f;
            float sA1 = 0.0f;
            float sD1 = 0.0f;
            for (int nf = 0; nf < 8; nf++) {
                int cb = n0 + wn * 64 + nf * 8 + (lane & 3) * 2;
                float s0v = Sv[cb];
                float s1v = Sv[cb + 1];
                float d0v = Dv[cb];
                float d1v = Dv[cb + 1];
                sA0 += acc[mf][nf][0] * s0v + acc[mf][nf][1] * s1v;
                sD0 += acc[mf][nf][0] * d0v + acc[mf][nf][1] * d1v;
                sA1 += acc[mf][nf][2] * s0v + acc[mf][nf][3] * s1v;
                sD1 += acc[mf][nf][2] * d0v + acc[mf][nf][3] * d1v;
            }
            for (int o = 1; o < 4; o <<= 1) {
                sA0 += __shfl_xor_sync(0xffffffffu, sA0, o);
                sD0 += __shfl_xor_sync(0xffffffffu, sD0, o);
                sA1 += __shfl_xor_sync(0xffffffffu, sA1, o);
                sD1 += __shfl_xor_sync(0xffffffffu, sD1, o);
            }
            if ((lane & 3) == 0) {
                int r0 = m0 + wm * 32 + mf * 16 + (lane >> 2);
                if (r0 < M) {
                    dotS[2 * r0 + head] = sA0;
                    dotD[2 * r0 + head] = sD0;
                }
                if (r0 + 8 < M) {
                    dotS[2 * (r0 + 8) + head] = sA1;
                    dotD[2 * (r0 + 8) + head] = sD1;
                }
            }
        }
    }
}

__device__ __forceinline__ float lrelu(float x)
{
    return (x > 0.0f) ? x : 0.2f * x;
}

__device__ __forceinline__ void online_upd(float e, float& m, float& s)
{
    if (e > m) {
        s = s * __expf(m - e) + 1.0f;
        m = e;
    } else {
        s += __expf(e - m);
    }
}

// ---------------- layer-1 aggregation (ELU + bf16 split out) -----------------
__global__ void gat_agg_l1_kernel(const float* __restrict__ asrc,
                                  const float* __restrict__ adst,
                                  const float* __restrict__ h,
                                  const float* __restrict__ bias,
                                  __nv_bfloat16* __restrict__ ohi,
                                  __nv_bfloat16* __restrict__ olo,
                                  int n_nodes)
{
    int w = (blockIdx.x * blockDim.x + threadIdx.x) >> 5;
    int lane = threadIdx.x & 31;
    if (w >= n_nodes) { return; }
    int s0 = g_off[w];
    int s1 = g_off[w + 1];
    float ad0 = adst[2 * w];
    float ad1 = adst[2 * w + 1];

    float m0 = -1e30f;
    float m1 = -1e30f;
    float sm0 = 0.0f;
    float sm1 = 0.0f;
    for (int i = s0 + lane; i < s1; i += 32) {
        int s = g_srcList[i];
        float e0 = lrelu(asrc[2 * s] + ad0);
        float e1 = lrelu(asrc[2 * s + 1] + ad1);
        online_upd(e0, m0, sm0);
        online_upd(e1, m1, sm1);
    }
    float M0 = m0;
    float M1 = m1;
    for (int o = 16; o > 0; o >>= 1) {
        M0 = fmaxf(M0, __shfl_xor_sync(0xffffffffu, M0, o));
        M1 = fmaxf(M1, __shfl_xor_sync(0xffffffffu, M1, o));
    }
    float t0 = sm0 * __expf(m0 - M0);
    float t1 = sm1 * __expf(m1 - M1);
    for (int o = 16; o > 0; o >>= 1) {
        t0 += __shfl_xor_sync(0xffffffffu, t0, o);
        t1 += __shfl_xor_sync(0xffffffffu, t1, o);
    }
    float inv0 = 1.0f / (t0 + 1e-16f);
    float inv1 = 1.0f / (t1 + 1e-16f);
    m0 = M0;
    m1 = M1;

    float acc0[4];
    float acc1[4];
    for (int v = 0; v < 4; v++) { acc0[v] = 0.0f; acc1[v] = 0.0f; }
    int i = s0;
    for (; i + 2 <= s1; i += 2) {
        int sa = g_srcList[i];
        int sb = g_srcList[i + 1];
        float wa0 = __expf(lrelu(asrc[2 * sa] + ad0) - m0) * inv0;
        float wa1 = __expf(lrelu(asrc[2 * sa + 1] + ad1) - m1) * inv1;
        float wb0 = __expf(lrelu(asrc[2 * sb] + ad0) - m0) * inv0;
        float wb1 = __expf(lrelu(asrc[2 * sb + 1] + ad1) - m1) * inv1;
        const float* ha = h + (size_t)sa * 256;
        const float* hb = h + (size_t)sb * 256;
        float4 a0 = *(const float4*)(ha + lane * 4);
        float4 a1 = *(const float4*)(ha + 128 + lane * 4);
        float4 b0 = *(const float4*)(hb + lane * 4);
        float4 b1 = *(const float4*)(hb + 128 + lane * 4);
        acc0[0] += wa0 * a0.x + wb0 * b0.x;
        acc0[1] += wa0 * a0.y + wb0 * b0.y;
        acc0[2] += wa0 * a0.z + wb0 * b0.z;
        acc0[3] += wa0 * a0.w + wb0 * b0.w;
        acc1[0] += wa1 * a1.x + wb1 * b1.x;
        acc1[1] += wa1 * a1.y + wb1 * b1.y;
        acc1[2] += wa1 * a1.z + wb1 * b1.z;
        acc1[3] += wa1 * a1.w + wb1 * b1.w;
    }
    if (i < s1) {
        int sa = g_srcList[i];
        float wa0 = __expf(lrelu(asrc[2 * sa] + ad0) - m0) * inv0;
        float wa1 = __expf(lrelu(asrc[2 * sa + 1] + ad1) - m1) * inv1;
        const float* ha = h + (size_t)sa * 256;
        float4 a0 = *(const float4*)(ha + lane * 4);
        float4 a1 = *(const float4*)(ha + 128 + lane * 4);
        acc0[0] += wa0 * a0.x;
        acc0[1] += wa0 * a0.y;
        acc0[2] += wa0 * a0.z;
        acc0[3] += wa0 * a0.w;
        acc1[0] += wa1 * a1.x;
        acc1[1] += wa1 * a1.y;
        acc1[2] += wa1 * a1.z;
        acc1[3] += wa1 * a1.w;
    }

    size_t base = (size_t)w * 256;
    for (int v = 0; v < 4; v++) {
        int c0 = lane * 4 + v;
        float r0 = acc0[v] + bias[c0];
        float r1 = acc1[v] + bias[128 + c0];
        r0 = (r0 > 0.0f) ? r0 : expm1f(r0);
        r1 = (r1 > 0.0f) ? r1 : expm1f(r1);
        __nv_bfloat16 h0 = __float2bfloat16(r0);
        __nv_bfloat16 h1 = __float2bfloat16(r1);
        ohi[base + c0] = h0;
        olo[base + c0] = __float2bfloat16(r0 - __bfloat162float(h0));
        ohi[base + 128 + c0] = h1;
        olo[base + 128 + c0] = __float2bfloat16(r1 - __bfloat162float(h1));
    }
}

// ---------------- layer-2 aggregation (mu | logstd, fp32 out) ----------------
__global__ void gat_agg_l2_kernel(const float* __restrict__ asrc,
                                  const float* __restrict__ adst,
                                  const float* __restrict__ h,
                                  const float* __restrict__ bmu,
                                  const float* __restrict__ bls,
                                  float* __restrict__ out_mu,
                                  float* __restrict__ out_ls,
                                  int n_nodes)
{
    int w = (blockIdx.x * blockDim.x + threadIdx.x) >> 5;
    int lane = threadIdx.x & 31;
    if (w >= n_nodes) { return; }
    int s0 = g_off[w];
    int s1 = g_off[w + 1];
    float ad0 = adst[2 * w];
    float ad1 = adst[2 * w + 1];

    float m0 = -1e30f;
    float m1 = -1e30f;
    float sm0 = 0.0f;
    float sm1 = 0.0f;
    for (int i = s0 + lane; i < s1; i += 32) {
        int s = g_srcList[i];
        float e0 = lrelu(asrc[2 * s] + ad0);
        float e1 = lrelu(asrc[2 * s + 1] + ad1);
        online_upd(e0, m0, sm0);
        online_upd(e1, m1, sm1);
    }
    float M0 = m0;
    float M1 = m1;
    for (int o = 16; o > 0; o >>= 1) {
        M0 = fmaxf(M0, __shfl_xor_sync(0xffffffffu, M0, o));
        M1 = fmaxf(M1, __shfl_xor_sync(0xffffffffu, M1, o));
    }
    float t0 = sm0 * __expf(m0 - M0);
    float t1 = sm1 * __expf(m1 - M1);
    for (int o = 16; o > 0; o >>= 1) {
        t0 += __shfl_xor_sync(0xffffffffu, t0, o);
        t1 += __shfl_xor_sync(0xffffffffu, t1, o);
    }
    float inv0 = 1.0f / (t0 + 1e-16f);
    float inv1 = 1.0f / (t1 + 1e-16f);
    m0 = M0;
    m1 = M1;

    float a00 = 0.0f;
    float a01 = 0.0f;
    float a10 = 0.0f;
    float a11 = 0.0f;
    int i = s0;
    for (; i + 2 <= s1; i += 2) {
        int sa = g_srcList[i];
        int sb = g_srcList[i + 1];
        float wa0 = __expf(lrelu(asrc[2 * sa] + ad0) - m0) * inv0;
        float wa1 = __expf(lrelu(asrc[2 * sa + 1] + ad1) - m1) * inv1;
        float wb0 = __expf(lrelu(asrc[2 * sb] + ad0) - m0) * inv0;
        float wb1 = __expf(lrelu(asrc[2 * sb + 1] + ad1) - m1) * inv1;
        const float* ha = h + (size_t)sa * 128;
        const float* hb = h + (size_t)sb * 128;
        float2 va0 = *(const float2*)(ha + lane * 2);
        float2 va1 = *(const float2*)(ha + 64 + lane * 2);
        float2 vb0 = *(const float2*)(hb + lane * 2);
        float2 vb1 = *(const float2*)(hb + 64 + lane * 2);
        a00 += wa0 * va0.x + wb0 * vb0.x;
        a01 += wa0 * va0.y + wb0 * vb0.y;
        a10 += wa1 * va1.x + wb1 * vb1.x;
        a11 += wa1 * va1.y + wb1 * vb1.y;
    }
    if (i < s1) {
        int sa = g_srcList[i];
        float wa0 = __expf(lrelu(asrc[2 * sa] + ad0) - m0) * inv0;
        float wa1 = __expf(lrelu(asrc[2 * sa + 1] + ad1) - m1) * inv1;
        const float* ha = h + (size_t)sa * 128;
        float2 va0 = *(const float2*)(ha + lane * 2);
        float2 va1 = *(const float2*)(ha + 64 + lane * 2);
        a00 += wa0 * va0.x;
        a01 += wa0 * va0.y;
        a10 += wa1 * va1.x;
        a11 += wa1 * va1.y;
    }
    float* o0 = out_mu + (size_t)w * 64 + lane * 2;
    float* o1 = out_ls + (size_t)w * 64 + lane * 2;
    o0[0] = a00 + bmu[lane * 2];
    o0[1] = a01 + bmu[lane * 2 + 1];
    o1[0] = a10 + bls[lane * 2];
    o1[1] = a11 + bls[lane * 2 + 1];
}

// ---------------- host launch ------------------------------------------------
static void* symaddr(const void* s)
{
    void* p = nullptr;
    cudaGetSymbolAddress(&p, s);
    return p;
}

extern "C" void kernel_launch(void* const* d_in, const int* in_sizes, int n_in,
                              void* d_out, int out_size)
{
    const float* x      = (const float*)d_in[0];
    const int*   ei     = (const int*)d_in[1];
    const float* W1     = (const float*)d_in[2];
    const float* attS1  = (const float*)d_in[3];
    const float* attD1  = (const float*)d_in[4];
    const float* b1     = (const float*)d_in[5];
    const float* Wmu    = (const float*)d_in[6];
    const float* attSmu = (const float*)d_in[7];
    const float* attDmu = (const float*)d_in[8];
    const float* bmu    = (const float*)d_in[9];
    const float* Wls    = (const float*)d_in[10];
    const float* attSls = (const float*)d_in[11];
    const float* attDls = (const float*)d_in[12];
    const float* bls    = (const float*)d_in[13];
    float* out = (float*)d_out;

    float* H1 = (float*)symaddr(g_H1);
    float* H2 = (float*)symaddr(g_H2);
    __nv_bfloat16* xhi   = (__nv_bfloat16*)symaddr(g_xhi);
    __nv_bfloat16* xlo   = (__nv_bfloat16*)symaddr(g_xlo);
    __nv_bfloat16* O1hi  = (__nv_bfloat16*)symaddr(g_O1hi);
    __nv_bfloat16* O1lo  = (__nv_bfloat16*)symaddr(g_O1lo);
    __nv_bfloat16* B1thi = (__nv_bfloat16*)symaddr(g_B1thi);
    __nv_bfloat16* B1tlo = (__nv_bfloat16*)symaddr(g_B1tlo);
    __nv_bfloat16* B2thi = (__nv_bfloat16*)symaddr(g_B2thi);
    __nv_bfloat16* B2tlo = (__nv_bfloat16*)symaddr(g_B2tlo);
    float* WA1 = (float*)symaddr(g_WA1);
    float* as1 = (float*)symaddr(g_as1);
    float* ad1 = (float*)symaddr(g_ad1);
    float* as2 = (float*)symaddr(g_as2);
    float* ad2 = (float*)symaddr(g_ad2);
    int* deg  = (int*)symaddr(g_deg);
    int* off  = (int*)symaddr(g_off);
    int* cur  = (int*)symaddr(g_cur);
    int* bsum = (int*)symaddr(g_blockSums);
    int* srcL = (int*)symaddr(g_srcList);
    float* S2 = (float*)symaddr(g_attS2);
    float* D2 = (float*)symaddr(g_attD2);

    const int N = NNODES;
    const int warpBlocks = (N * 32 + 255) / 256;
    const int mtiles = (N + 127) / 128;  // 391

    cudaFuncSetAttribute(gemm_mma_kernel<4, false>,
                         cudaFuncAttributeMaxDynamicSharedMemorySize, GEMM_SMEM);
    cudaFuncSetAttribute(gemm_mma_kernel<8, true>,
                         cudaFuncAttributeMaxDynamicSharedMemorySize, GEMM_SMEM);

    // launches 1..3: prep (gemm1 lands at profiled slot 4)
    packW1_kernel<<<(256 * 128 + 255) / 256, 256>>>(W1, B1thi, B1tlo);
    packW2_kernel<<<131, 256>>>(Wmu, Wls, B2thi, B2tlo,
                                W1, attS1, attD1,
                                attSmu, attSls, attDmu, attDls,
                                WA1, S2, D2);
    split_dots_kernel<<<(N + 1) / 2, 256>>>(x, WA1, xhi, xlo, as1, ad1);

    // launch 4: layer-1 GEMM: H1 = x @ W1 (128x128 tiles; N=256 -> 2 col-tiles)
    gemm_mma_kernel<4, false><<<dim3(2, mtiles), 256, GEMM_SMEM>>>(
        xhi, xlo, B1thi, B1tlo, H1, N, 256,
        (const float*)0, (const float*)0, (float*)0, (float*)0);

    // CSR build (multi-block scan)
    zero_int_kernel<<<(N + 1 + 255) / 256, 256>>>(deg, N + 1);
    hist_kernel<<<(E_TOT + 255) / 256, 256>>>(ei, deg);
    scanA_kernel<<<SCAN_BLOCKS, 256>>>(deg, off, bsum);
    scanB_kernel<<<1, 256>>>(bsum);
    scanC_kernel<<<SCAN_BLOCKS, 256>>>(off, bsum, cur);
    scatter_kernel<<<(E_TOT + 255) / 256, 256>>>(ei, cur, srcL);

    gat_agg_l1_kernel<<<warpBlocks, 256>>>(as1, ad1, H1, b1, O1hi, O1lo, N);

    // layer-2 GEMM with fused attention dots (plain stores into as2/ad2)
    gemm_mma_kernel<8, true><<<dim3(1, mtiles), 256, GEMM_SMEM>>>(
        O1hi, O1lo, B2thi, B2tlo, H2, N, 128,
        S2, D2, as2, ad2);

    gat_agg_l2_kernel<<<warpBlocks, 256>>>(as2, ad2, H2, bmu, bls,
                                           out, out + (size_t)N * 64, N);
}